// round 13
// baseline (speedup 1.0000x reference)
#include <cuda_runtime.h>
#include <cuda_fp16.h>
#include <stdint.h>

// ============================================================================
// Int8Linear — harness dtypes: x fp16->float32, w int8->int32, out fp16->float32.
//   out[m,n] = f32( fp16( fp32acc( x[m,:] . w[n,:] ) * scale[n] ) )
// M=8192, N=11008, K=4096.
// Round 13: round 12 (int8-through-SMEM W in mma-fragment order, in-register
// exact convert) with the prep_w GRID FIX: 44032 blocks (was 11008 -> only
// 1/4 of the fragment image initialized, rel_err 0.86).
// CTA 128x128, warp 64x32, 2 CTAs/SM, 4-stage cp.async, SW128 A.
// ============================================================================

namespace {

constexpr int GM = 8192;
constexpr int GN = 11008;
constexpr int GK = 4096;
constexpr int BM = 128;
constexpr int BN = 128;
constexpr int BK = 64;                    // 64 fp16 = 128B row (SW128 atom)
constexpr int KIT = GK / BK;              // 64
constexpr int NT = GN / BN;               // 86
constexpr int MT = GM / BM;               // 64
constexpr int KTILES = GK / BK;           // 64 k-tiles per n-tile row
constexpr int STAGES = 4;
constexpr int TILE_A = BM * 128;          // 16 KB fp16 A (swizzled rows)
constexpr int TILE_W = BN * BK;           // 8 KB int8 W (fragment-major)
constexpr int STAGE_B = TILE_A + TILE_W;  // 24 KB
constexpr int SMEM_BYTES = 1024 + STAGES * STAGE_B;  // 99328 B (x2 CTAs fits)

__device__ __align__(1024) __half   g_xh[(size_t)GM * GK];          // 64 MB fp16
__device__ __align__(1024) uint32_t g_w8[(size_t)GN * GK / 4];      // 45 MB int8 frags

#define SW128(o) ((o) ^ (((o) >> 3) & 0x70u))

__device__ __forceinline__ uint32_t smem_u32(const void* p) {
    uint32_t a;
    asm("{ .reg .u64 t; cvta.to.shared.u64 t, %1; cvt.u32.u64 %0, t; }"
        : "=r"(a) : "l"(p));
    return a;
}

// exact packed-int8x4 -> 2x half2: ((b^0x80)|0x6400) - 1152
// h2[0] = {f16(byte0), f16(byte1)}, h2[1] = {f16(byte2), f16(byte3)}
__device__ __forceinline__ void cvt4_i8_f16(uint32_t v, uint32_t* h2) {
    const uint32_t u = v ^ 0x80808080u;
    uint32_t lo = __byte_perm(u, 0x64646464u, 0x4140);
    uint32_t hi = __byte_perm(u, 0x64646464u, 0x4342);
    const uint32_t bias_u = 0x64806480u;  // half2(1152, 1152)
    __half2 a = __hsub2(*reinterpret_cast<const __half2*>(&lo),
                        *reinterpret_cast<const __half2*>(&bias_u));
    __half2 c = __hsub2(*reinterpret_cast<const __half2*>(&hi),
                        *reinterpret_cast<const __half2*>(&bias_u));
    h2[0] = *reinterpret_cast<uint32_t*>(&a);
    h2[1] = *reinterpret_cast<uint32_t*>(&c);
}

// ---------------------------------------------------------------------------
__global__ void __launch_bounds__(256) prep_x(const float* __restrict__ x) {
    const size_t e = ((size_t)blockIdx.x * 256 + threadIdx.x) * 8;
    float4 f0 = *reinterpret_cast<const float4*>(x + e);
    float4 f1 = *reinterpret_cast<const float4*>(x + e + 4);
    __half2 h0 = __floats2half2_rn(f0.x, f0.y);
    __half2 h1 = __floats2half2_rn(f0.z, f0.w);
    __half2 h2 = __floats2half2_rn(f1.x, f1.y);
    __half2 h3 = __floats2half2_rn(f1.z, f1.w);
    uint4 st;
    st.x = *reinterpret_cast<uint32_t*>(&h0);
    st.y = *reinterpret_cast<uint32_t*>(&h1);
    st.z = *reinterpret_cast<uint32_t*>(&h2);
    st.w = *reinterpret_cast<uint32_t*>(&h3);
    *reinterpret_cast<uint4*>(g_xh + e) = st;
}

// prep_w: int32 weights -> int8 words in mma-B-fragment order.
// word wi: block = wi>>11 (ntile*KTILES + ktile), inner = wi&2047,
//   k16 = inner>>9, n8 = (inner>>5)&15, lane = inner&31.
//   n  = ntile*128 + n8*8 + lane/4
//   ka = ktile*64 + k16*16 + (lane%4)*2
//   word bytes = { w[n][ka], w[n][ka+1], w[n][ka+8], w[n][ka+9] } (low bytes)
__global__ void __launch_bounds__(256) prep_w(const int* __restrict__ w) {
    const size_t wi    = (size_t)blockIdx.x * 256 + threadIdx.x;
    const int    inner = (int)(wi & 2047);
    const size_t block = wi >> 11;
    const int    ktile = (int)(block & (KTILES - 1));
    const int    ntile = (int)(block >> 6);        // KTILES = 64
    const int    k16   = inner >> 9;
    const int    n8    = (inner >> 5) & 15;
    const int    lane  = inner & 31;
    const int    n     = ntile * 128 + n8 * 8 + (lane >> 2);
    const int    ka    = ktile * 64 + k16 * 16 + (lane & 3) * 2;
    const int*   src   = w + (size_t)n * GK + ka;
    uint32_t v0 = (uint32_t)src[0];
    uint32_t v1 = (uint32_t)src[1];
    uint32_t v8 = (uint32_t)src[8];
    uint32_t v9 = (uint32_t)src[9];
    uint32_t t = __byte_perm(v0, v1, 0x0040);      // {b0, b1} in low half
    uint32_t u = __byte_perm(v8, v9, 0x0040);      // {b8, b9} in low half
    g_w8[wi] = __byte_perm(t, u, 0x5410);          // {b0, b1, b8, b9}
}

// ---------------------------------------------------------------------------
__device__ __forceinline__ void cpa16(uint32_t dst, const void* src) {
    asm volatile("cp.async.cg.shared.global [%0], [%1], 16;"
                 :: "r"(dst), "l"(src) : "memory");
}
__device__ __forceinline__ void cp_commit() {
    asm volatile("cp.async.commit_group;" ::: "memory");
}
template <int N>
__device__ __forceinline__ void cp_wait() {
    asm volatile("cp.async.wait_group %0;" :: "n"(N) : "memory");
}
__device__ __forceinline__ void ldsm4(uint32_t* r, uint32_t addr) {
    asm volatile("ldmatrix.sync.aligned.m8n8.x4.shared.b16 {%0,%1,%2,%3}, [%4];"
                 : "=r"(r[0]), "=r"(r[1]), "=r"(r[2]), "=r"(r[3]) : "r"(addr));
}
__device__ __forceinline__ uint32_t lds32(uint32_t addr) {
    uint32_t v;
    asm volatile("ld.shared.b32 %0, [%1];" : "=r"(v) : "r"(addr));
    return v;
}
__device__ __forceinline__ void mma16816(float* c, const uint32_t* a,
                                         uint32_t b0, uint32_t b1) {
    asm volatile(
        "mma.sync.aligned.m16n8k16.row.col.f32.f16.f16.f32 "
        "{%0,%1,%2,%3}, {%4,%5,%6,%7}, {%8,%9}, {%0,%1,%2,%3};"
        : "+f"(c[0]), "+f"(c[1]), "+f"(c[2]), "+f"(c[3])
        : "r"(a[0]), "r"(a[1]), "r"(a[2]), "r"(a[3]), "r"(b0), "r"(b1));
}

__global__ void __launch_bounds__(256, 2)
gemm_kernel(const float* __restrict__ scale, float* __restrict__ out) {
    extern __shared__ char smem[];
    const uint32_t raw   = smem_u32(smem);
    const uint32_t tiles = (raw + 1023u) & ~1023u;   // 1KB align for SW128

    const int tid  = threadIdx.x;
    const int lane = tid & 31;
    const int warp = tid >> 5;
    const int wm   = warp >> 2;   // 0..1  (64 m-rows each)
    const int wn   = warp & 3;    // 0..3  (32 n-cols each)
    const int n0   = blockIdx.x * BN;   // N fastest -> W image L2-resident
    const int m0   = blockIdx.y * BM;

    const __half*   ag = g_xh + (size_t)m0 * GK;
    const uint32_t* bg = g_w8 + (size_t)blockIdx.x * (KTILES * (TILE_W / 4));

    // A: 1024 16B-units (4/thread); W frags: 512 16B-units (2/thread), linear
    auto issue = [&](int kn) {
        const int s  = kn & (STAGES - 1);
        const int k0 = kn * BK;
        const uint32_t ab = tiles + s * STAGE_B;
        const uint32_t bb = ab + TILE_A;
#pragma unroll
        for (int p = 0; p < 4; ++p) {
            const int u = tid + p * 256;
            const int row = u >> 3, c = u & 7;
            const uint32_t o = SW128((uint32_t)(row * 128 + c * 16));
            cpa16(ab + o, ag + (size_t)row * GK + k0 + c * 8);
        }
        const uint32_t* wsrc = bg + (size_t)kn * (TILE_W / 4);
#pragma unroll
        for (int p = 0; p < 2; ++p) {
            const int u = tid + p * 256;
            cpa16(bb + u * 16, wsrc + u * 4);
        }
        cp_commit();
    };

    issue(0); issue(1); issue(2);

    float acc[4][4][4];
#pragma unroll
    for (int t = 0; t < 4; ++t)
#pragma unroll
        for (int j = 0; j < 4; ++j)
#pragma unroll
            for (int e = 0; e < 4; ++e) acc[t][j][e] = 0.f;

    // A ldsm per-lane address components (halves)
    const int row_a = wm * 64 + (lane & 15);      // + t*16
    const int ka    = (lane >> 4) << 3;

    for (int it = 0; it < KIT; ++it) {
        const int s = it & (STAGES - 1);

        cp_wait<2>();          // stage `it` complete (in-order groups)
        __syncthreads();       // visible CTA-wide; stage (it-1)&3 fully read

        if (it + 3 < KIT) issue(it + 3);
        else              cp_commit();   // keep group count invariant

        const uint32_t abase = tiles + s * STAGE_B;
        const uint32_t bbase = abase + TILE_A;

#pragma unroll
        for (int st = 0; st < 4; ++st) {           // 4 x k16 per BK=64
            const int k2 = st * 16;
            uint32_t a[4][4], b[4][2];
#pragma unroll
            for (int t = 0; t < 4; ++t) {
                const uint32_t o = (uint32_t)((row_a + t * 16) * 128 + (k2 + ka) * 2);
                ldsm4(a[t], abase + SW128(o));
            }
            // W frags: block (st*16 + wn*4 + j), word index lane
#pragma unroll
            for (int j = 0; j < 4; ++j) {
                const uint32_t w8 = lds32(bbase +
                    (uint32_t)(((st * 16 + wn * 4 + j) * 32 + lane) * 4));
                cvt4_i8_f16(w8, b[j]);
            }
#pragma unroll
            for (int t = 0; t < 4; ++t)
#pragma unroll
                for (int j = 0; j < 4; ++j)
                    mma16816(acc[t][j], a[t], b[j][0], b[j][1]);
        }
        // no trailing barrier: next iteration's wait+barrier orders reuse
    }

    // ---- epilogue: scale, fp16 round (match reference), fp32 store ----
    const int mrow = m0 + wm * 64 + (lane >> 2);
    const int ncol = n0 + wn * 32 + (lane & 3) * 2;
    float* og = out + (size_t)mrow * GN + ncol;
    const float* scp = scale + ncol;

#pragma unroll
    for (int t = 0; t < 4; ++t) {
#pragma unroll
        for (int j = 0; j < 4; ++j) {
            const float2 sc = *reinterpret_cast<const float2*>(scp + j * 8);
            float2 r0, r1;
            r0.x = __half2float(__float2half_rn(acc[t][j][0] * sc.x));
            r0.y = __half2float(__float2half_rn(acc[t][j][1] * sc.y));
            r1.x = __half2float(__float2half_rn(acc[t][j][2] * sc.x));
            r1.y = __half2float(__float2half_rn(acc[t][j][3] * sc.y));
            *reinterpret_cast<float2*>(og + (size_t)(t * 16) * GN + j * 8)     = r0;
            *reinterpret_cast<float2*>(og + (size_t)(t * 16 + 8) * GN + j * 8) = r1;
        }
    }
}

}  // namespace

extern "C" void kernel_launch(void* const* d_in, const int* in_sizes, int n_in,
                              void* d_out, int out_size) {
    const float* x     = (const float*)d_in[0];
    const int*   w     = (const int*)d_in[1];
    const float* scale = (const float*)d_in[2];
    float*       out   = (float*)d_out;

    cudaFuncSetAttribute(gemm_kernel,
                         cudaFuncAttributeMaxDynamicSharedMemorySize, SMEM_BYTES);

    prep_x<<<GM * GK / 8 / 256, 256>>>(x);              // 16384 blocks
    prep_w<<<GN * GK / 4 / 256, 256>>>((const int*)w);  // 44032 blocks (FIXED)
    gemm_kernel<<<dim3(NT, MT), 256, SMEM_BYTES>>>(scale, out);
}

// round 14
// speedup vs baseline: 1.0246x; 1.0246x over previous
#include <cuda_runtime.h>
#include <cuda_fp16.h>
#include <stdint.h>

// ============================================================================
// Int8Linear — harness dtypes: x fp16->float32, w int8->int32, out fp16->float32.
//   out[m,n] = f32( fp16( fp32acc( x[m,:] . w[n,:] ) * scale[n] ) )
// M=8192, N=11008, K=4096.
// Round 14: int8 W through SMEM (crossbar savings of R13) with fixed issue
// texture: per-substep single LDS.128 fetches all 4 B-fragment words,
// prefetched one substep ahead; converts are compiler-scheduled plain ops.
// CTA 128x128, warp 64x32, 2 CTAs/SM, 4-stage cp.async, SW128 A.
// ============================================================================

namespace {

constexpr int GM = 8192;
constexpr int GN = 11008;
constexpr int GK = 4096;
constexpr int BM = 128;
constexpr int BN = 128;
constexpr int BK = 64;                    // 64 fp16 = 128B row (SW128 atom)
constexpr int KIT = GK / BK;              // 64
constexpr int NT = GN / BN;               // 86
constexpr int MT = GM / BM;               // 64
constexpr int KTILES = GK / BK;           // 64
constexpr int STAGES = 4;
constexpr int TILE_A = BM * 128;          // 16 KB fp16 A (swizzled rows)
constexpr int TILE_W = BN * BK;           // 8 KB int8 W (fragment-major)
constexpr int WWORDS = TILE_W / 4;        // 2048 words per (ntile,ktile) block
constexpr int STAGE_B = TILE_A + TILE_W;  // 24 KB
constexpr int SMEM_BYTES = 1024 + STAGES * STAGE_B;  // 99328 B (x2 CTAs fits)

__device__ __align__(1024) __half   g_xh[(size_t)GM * GK];      // 64 MB fp16
__device__ __align__(1024) uint32_t g_w8[(size_t)GN * GK / 4];  // 45 MB int8 frags

#define SW128(o) ((o) ^ (((o) >> 3) & 0x70u))

__device__ __forceinline__ uint32_t smem_u32(const void* p) {
    uint32_t a;
    asm("{ .reg .u64 t; cvta.to.shared.u64 t, %1; cvt.u32.u64 %0, t; }"
        : "=r"(a) : "l"(p));
    return a;
}

// exact packed-int8x4 -> 2x half2: ((b^0x80)|0x6400) - 1152
// h2[0] = {f16(byte0), f16(byte1)}, h2[1] = {f16(byte2), f16(byte3)}
__device__ __forceinline__ void cvt4_i8_f16(uint32_t v, uint32_t* h2) {
    const uint32_t u = v ^ 0x80808080u;
    uint32_t lo = __byte_perm(u, 0x64646464u, 0x4140);
    uint32_t hi = __byte_perm(u, 0x64646464u, 0x4342);
    const uint32_t bias_u = 0x64806480u;  // half2(1152, 1152)
    __half2 a = __hsub2(*reinterpret_cast<const __half2*>(&lo),
                        *reinterpret_cast<const __half2*>(&bias_u));
    __half2 c = __hsub2(*reinterpret_cast<const __half2*>(&hi),
                        *reinterpret_cast<const __half2*>(&bias_u));
    h2[0] = *reinterpret_cast<uint32_t*>(&a);
    h2[1] = *reinterpret_cast<uint32_t*>(&c);
}

// ---------------------------------------------------------------------------
__global__ void __launch_bounds__(256) prep_x(const float* __restrict__ x) {
    const size_t e = ((size_t)blockIdx.x * 256 + threadIdx.x) * 8;
    float4 f0 = *reinterpret_cast<const float4*>(x + e);
    float4 f1 = *reinterpret_cast<const float4*>(x + e + 4);
    __half2 h0 = __floats2half2_rn(f0.x, f0.y);
    __half2 h1 = __floats2half2_rn(f0.z, f0.w);
    __half2 h2 = __floats2half2_rn(f1.x, f1.y);
    __half2 h3 = __floats2half2_rn(f1.z, f1.w);
    uint4 st;
    st.x = *reinterpret_cast<uint32_t*>(&h0);
    st.y = *reinterpret_cast<uint32_t*>(&h1);
    st.z = *reinterpret_cast<uint32_t*>(&h2);
    st.w = *reinterpret_cast<uint32_t*>(&h3);
    *reinterpret_cast<uint4*>(g_xh + e) = st;
}

// prep_w: int32 weights -> int8 words, fragment-major, LDS.128-friendly:
// word index within (ntile,ktile) block of 2048:
//   idx = wn*512 + st*128 + lane*4 + j     (wn,st in 0..3; lane 0..31; j 0..3)
// maps to mma B fragment: nb = wn*4+j, k16 = st:
//   n  = ntile*128 + nb*8 + lane/4
//   ka = ktile*64  + st*16 + (lane%4)*2
//   bytes = { w[n][ka], w[n][ka+1], w[n][ka+8], w[n][ka+9] }
__global__ void __launch_bounds__(256) prep_w(const int* __restrict__ w) {
    const size_t wi    = (size_t)blockIdx.x * 256 + threadIdx.x;
    const int    inner = (int)(wi & 2047);
    const size_t block = wi >> 11;
    const int    ktile = (int)(block & (KTILES - 1));
    const int    ntile = (int)(block >> 6);        // KTILES = 64
    const int    wn    = inner >> 9;
    const int    st    = (inner >> 7) & 3;
    const int    lane  = (inner >> 2) & 31;
    const int    j     = inner & 3;
    const int    nb    = wn * 4 + j;
    const int    n     = ntile * 128 + nb * 8 + (lane >> 2);
    const int    ka    = ktile * 64 + st * 16 + (lane & 3) * 2;
    const int*   src   = w + (size_t)n * GK + ka;
    uint32_t v0 = (uint32_t)src[0];
    uint32_t v1 = (uint32_t)src[1];
    uint32_t v8 = (uint32_t)src[8];
    uint32_t v9 = (uint32_t)src[9];
    uint32_t t = __byte_perm(v0, v1, 0x0040);      // {b0, b1} low half
    uint32_t u = __byte_perm(v8, v9, 0x0040);      // {b8, b9} low half
    g_w8[wi] = __byte_perm(t, u, 0x5410);          // {b0, b1, b8, b9}
}

// ---------------------------------------------------------------------------
__device__ __forceinline__ void cpa16(uint32_t dst, const void* src) {
    asm volatile("cp.async.cg.shared.global [%0], [%1], 16;"
                 :: "r"(dst), "l"(src) : "memory");
}
__device__ __forceinline__ void cp_commit() {
    asm volatile("cp.async.commit_group;" ::: "memory");
}
template <int N>
__device__ __forceinline__ void cp_wait() {
    asm volatile("cp.async.wait_group %0;" :: "n"(N) : "memory");
}
__device__ __forceinline__ void ldsm4(uint32_t* r, uint32_t addr) {
    asm volatile("ldmatrix.sync.aligned.m8n8.x4.shared.b16 {%0,%1,%2,%3}, [%4];"
                 : "=r"(r[0]), "=r"(r[1]), "=r"(r[2]), "=r"(r[3]) : "r"(addr));
}
__device__ __forceinline__ uint4 lds128(uint32_t addr) {
    uint4 v;
    asm volatile("ld.shared.v4.b32 {%0,%1,%2,%3}, [%4];"
                 : "=r"(v.x), "=r"(v.y), "=r"(v.z), "=r"(v.w) : "r"(addr));
    return v;
}
__device__ __forceinline__ void mma16816(float* c, const uint32_t* a,
                                         uint32_t b0, uint32_t b1) {
    asm volatile(
        "mma.sync.aligned.m16n8k16.row.col.f32.f16.f16.f32 "
        "{%0,%1,%2,%3}, {%4,%5,%6,%7}, {%8,%9}, {%0,%1,%2,%3};"
        : "+f"(c[0]), "+f"(c[1]), "+f"(c[2]), "+f"(c[3])
        : "r"(a[0]), "r"(a[1]), "r"(a[2]), "r"(a[3]), "r"(b0), "r"(b1));
}

__global__ void __launch_bounds__(256, 2)
gemm_kernel(const float* __restrict__ scale, float* __restrict__ out) {
    extern __shared__ char smem[];
    const uint32_t raw   = smem_u32(smem);
    const uint32_t tiles = (raw + 1023u) & ~1023u;   // 1KB align for SW128

    const int tid  = threadIdx.x;
    const int lane = tid & 31;
    const int warp = tid >> 5;
    const int wm   = warp >> 2;   // 0..1  (64 m-rows each)
    const int wn   = warp & 3;    // 0..3  (32 n-cols each)
    const int n0   = blockIdx.x * BN;   // N fastest -> W image L2-resident
    const int m0   = blockIdx.y * BM;

    const __half*   ag = g_xh + (size_t)m0 * GK;
    const uint32_t* bg = g_w8 + (size_t)blockIdx.x * ((size_t)KTILES * WWORDS);

    // A: 1024 16B-units (4/thread); W frags: 512 16B-units (2/thread), linear
    auto issue = [&](int kn) {
        const int s  = kn & (STAGES - 1);
        const int k0 = kn * BK;
        const uint32_t ab = tiles + s * STAGE_B;
        const uint32_t bb = ab + TILE_A;
#pragma unroll
        for (int p = 0; p < 4; ++p) {
            const int u = tid + p * 256;
            const int row = u >> 3, c = u & 7;
            const uint32_t o = SW128((uint32_t)(row * 128 + c * 16));
            cpa16(ab + o, ag + (size_t)row * GK + k0 + c * 8);
        }
        const uint32_t* wsrc = bg + (size_t)kn * WWORDS;
#pragma unroll
        for (int p = 0; p < 2; ++p) {
            const int u = tid + p * 256;
            cpa16(bb + u * 16, wsrc + u * 4);
        }
        cp_commit();
    };

    issue(0); issue(1); issue(2);

    float acc[4][4][4];
#pragma unroll
    for (int t = 0; t < 4; ++t)
#pragma unroll
        for (int j = 0; j < 4; ++j)
#pragma unroll
            for (int e = 0; e < 4; ++e) acc[t][j][e] = 0.f;

    // A ldsm per-lane address components (halves)
    const int row_a = wm * 64 + (lane & 15);      // + t*16
    const int ka    = (lane >> 4) << 3;
    // W per-warp lds128 base offset within the W tile (bytes)
    const uint32_t woff = (uint32_t)(wn * 2048 + lane * 16);

    for (int it = 0; it < KIT; ++it) {
        const int s = it & (STAGES - 1);

        cp_wait<2>();          // stage `it` complete (in-order groups)
        __syncthreads();       // visible CTA-wide; stage (it-1)&3 fully read

        if (it + 3 < KIT) issue(it + 3);
        else              cp_commit();   // keep group count invariant

        const uint32_t abase = tiles + s * STAGE_B;
        const uint32_t bbase = abase + TILE_A + woff;

        uint4 w4 = lds128(bbase);        // W words for substep 0

#pragma unroll
        for (int st = 0; st < 4; ++st) {
            const int k2 = st * 16;
            uint32_t a[4][4];
#pragma unroll
            for (int t = 0; t < 4; ++t) {
                const uint32_t o = (uint32_t)((row_a + t * 16) * 128 + (k2 + ka) * 2);
                ldsm4(a[t], abase + SW128(o));
            }
            uint4 w4n;
            if (st < 3) w4n = lds128(bbase + (uint32_t)((st + 1) * 512));

            // compiler-scheduled converts (consume w4 loaded one substep ago)
            uint32_t b[4][2];
            cvt4_i8_f16(w4.x, b[0]);
            cvt4_i8_f16(w4.y, b[1]);
            cvt4_i8_f16(w4.z, b[2]);
            cvt4_i8_f16(w4.w, b[3]);

#pragma unroll
            for (int t = 0; t < 4; ++t)
#pragma unroll
                for (int j = 0; j < 4; ++j)
                    mma16816(acc[t][j], a[t], b[j][0], b[j][1]);

            w4 = w4n;
        }
        // no trailing barrier: next iteration's wait+barrier orders reuse
    }

    // ---- epilogue: scale, fp16 round (match reference), fp32 store ----
    const int mrow = m0 + wm * 64 + (lane >> 2);
    const int ncol = n0 + wn * 32 + (lane & 3) * 2;
    float* og = out + (size_t)mrow * GN + ncol;
    const float* scp = scale + ncol;

#pragma unroll
    for (int t = 0; t < 4; ++t) {
#pragma unroll
        for (int j = 0; j < 4; ++j) {
            const float2 sc = *reinterpret_cast<const float2*>(scp + j * 8);
            float2 r0, r1;
            r0.x = __half2float(__float2half_rn(acc[t][j][0] * sc.x));
            r0.y = __half2float(__float2half_rn(acc[t][j][1] * sc.y));
            r1.x = __half2float(__float2half_rn(acc[t][j][2] * sc.x));
            r1.y = __half2float(__float2half_rn(acc[t][j][3] * sc.y));
            *reinterpret_cast<float2*>(og + (size_t)(t * 16) * GN + j * 8)     = r0;
            *reinterpret_cast<float2*>(og + (size_t)(t * 16 + 8) * GN + j * 8) = r1;
        }
    }
}

}  // namespace

extern "C" void kernel_launch(void* const* d_in, const int* in_sizes, int n_in,
                              void* d_out, int out_size) {
    const float* x     = (const float*)d_in[0];
    const int*   w     = (const int*)d_in[1];
    const float* scale = (const float*)d_in[2];
    float*       out   = (float*)d_out;

    cudaFuncSetAttribute(gemm_kernel,
                         cudaFuncAttributeMaxDynamicSharedMemorySize, SMEM_BYTES);

    prep_x<<<GM * GK / 8 / 256, 256>>>(x);              // 16384 blocks
    prep_w<<<GN * GK / 4 / 256, 256>>>((const int*)w);  // 44032 blocks
    gemm_kernel<<<dim3(NT, MT), 256, SMEM_BYTES>>>(scale, out);
}